// round 3
// baseline (speedup 1.0000x reference)
#include <cuda_runtime.h>
#include <math.h>

#define N       4096
#define NFEAT   512
#define NHID    64
#define NHEADS  8
#define NCLASS  16
#define HD      512   /* NHEADS*NHID */

// ---------------- scratch (device globals; no allocations) ----------------
__device__ unsigned g_adj[N * 128];            // bit j of row i -> g_adj[i*128 + (j>>5)] >> (j&31)
__device__ float g_W1r[NFEAT * HD];            // [f][h*64+k]
__device__ float g_Wh1[N * HD];                // [i][h*64+k]
__device__ float g_fs1[N * NHEADS];            // raw src logit
__device__ float g_fd1[N * NHEADS];            // raw dst logit
__device__ float g_ed1[N * NHEADS];            // exp(fd)
__device__ float g_ed1b[N * NHEADS];           // exp(0.2*fd)
__device__ float g_hcat[N * HD];               // layer-1 output (post ELU)
__device__ float g_Wh2[N * NCLASS];
__device__ float g_fs2[N], g_fd2[N], g_ed2[N], g_ed2b[N];

// ---------------- K0: pack adjacency into bitmask ----------------
__global__ void k_pack(const int* __restrict__ adj) {
    int i = blockIdx.x;
    int t = threadIdx.x;                       // 1024 threads
    for (int base = 0; base < N; base += 1024) {
        int j = base + t;
        int v = adj[(size_t)i * N + j];
        unsigned m = __ballot_sync(0xffffffffu, v > 0);
        if ((t & 31) == 0) g_adj[i * 128 + (j >> 5)] = m;
    }
}

// ---------------- K0b: rearrange W1[h][f][k] -> W1r[f][h*64+k] ----------------
__global__ void k_w1r(const float* __restrict__ W1) {
    int idx = blockIdx.x * 256 + threadIdx.x;  // 262144 total
    int k = idx & 63;
    int f = (idx >> 6) & 511;
    int h = idx >> 15;
    g_W1r[f * HD + h * 64 + k] = W1[idx];
}

// ---------------- K1: Wh1 = x @ W1r   (4096x512 @ 512x512) ----------------
__global__ __launch_bounds__(256) void k_gemm1(const float* __restrict__ x) {
    __shared__ float As[16 * 68];   // [k][row], padded
    __shared__ float Bs[16 * 64];   // [k][col]
    int m0 = blockIdx.x * 64, n0 = blockIdx.y * 64;
    int t = threadIdx.x;
    int tr = t >> 4, tc = t & 15;
    float acc[4][4] = {};
    for (int kk = 0; kk < NFEAT; kk += 16) {
        {   // load A tile 64 rows x 16 k
            int c = t & 15, r0 = t >> 4;
            #pragma unroll
            for (int rr = 0; rr < 4; rr++) {
                int r = r0 + rr * 16;
                As[c * 68 + r] = x[(size_t)(m0 + r) * NFEAT + kk + c];
            }
        }
        {   // load B tile 16 k x 64 n
            int n = t & 63, k0 = t >> 6;
            #pragma unroll
            for (int q = 0; q < 4; q++) {
                int k = k0 + q * 4;
                Bs[k * 64 + n] = g_W1r[(size_t)(kk + k) * HD + n0 + n];
            }
        }
        __syncthreads();
        #pragma unroll
        for (int k = 0; k < 16; k++) {
            float4 a4 = *(const float4*)&As[k * 68 + tr * 4];
            float4 b4 = *(const float4*)&Bs[k * 64 + tc * 4];
            float av[4] = {a4.x, a4.y, a4.z, a4.w};
            float bv[4] = {b4.x, b4.y, b4.z, b4.w};
            #pragma unroll
            for (int i = 0; i < 4; i++)
                #pragma unroll
                for (int j = 0; j < 4; j++) acc[i][j] += av[i] * bv[j];
        }
        __syncthreads();
    }
    #pragma unroll
    for (int i = 0; i < 4; i++) {
        int row = m0 + tr * 4 + i;
        float4 v = make_float4(acc[i][0], acc[i][1], acc[i][2], acc[i][3]);
        *(float4*)&g_Wh1[(size_t)row * HD + n0 + tc * 4] = v;
    }
}

// ---------------- K1b: layer-1 attention logits + exp tables ----------------
__global__ void k_logit1(const float* __restrict__ a1) {
    int i = blockIdx.x;
    int w = threadIdx.x >> 5, l = threadIdx.x & 31;   // warp w = head w
    const float* wh = &g_Wh1[(size_t)i * HD + w * 64];
    const float* a  = &a1[w * 128];
    float s = wh[l] * a[l]      + wh[l + 32] * a[l + 32];
    float d = wh[l] * a[64 + l] + wh[l + 32] * a[96 + l];
    #pragma unroll
    for (int o = 16; o; o >>= 1) {
        s += __shfl_xor_sync(0xffffffffu, s, o);
        d += __shfl_xor_sync(0xffffffffu, d, o);
    }
    if (l == 0) {
        g_fs1[i * 8 + w]  = s;
        g_fd1[i * 8 + w]  = d;
        g_ed1[i * 8 + w]  = expf(d);
        g_ed1b[i * 8 + w] = expf(0.2f * d);
    }
}

// ---------------- K2: fused masked-softmax attention, layer 1 ----------------
// 16 rows per block; 512 threads. Phase A builds P tile (32 j x 8 h x 16 r),
// Phase B: each thread owns output o = h*64+k and accumulates 16 rows with
// packed fp32x2 FMA. Epilogue: /Z then ELU.
#define RI 16
#define CJ 32
__global__ __launch_bounds__(512) void k_att1(void) {
    __shared__ unsigned sAdj[RI][128];
    __shared__ float sP[CJ][128];          // [jj][h*16 + r]
    __shared__ float sZ[RI][8];
    __shared__ float sFs[RI][8], sEi[RI][8], sEib[RI][8];

    int i0 = blockIdx.x * RI;
    int t = threadIdx.x;

    for (int idx = t; idx < RI * 128; idx += 512)
        sAdj[idx >> 7][idx & 127] = g_adj[(size_t)(i0 + (idx >> 7)) * 128 + (idx & 127)];
    if (t < RI * 8) {
        int r = t >> 3, h = t & 7;
        float fs = g_fs1[(i0 + r) * 8 + h];
        sFs[r][h] = fs;
        sEi[r][h] = expf(fs);
        sEib[r][h] = expf(0.2f * fs);
        sZ[r][h] = 0.f;
    }
    __syncthreads();

    int jj = t >> 4, r = t & 15;          // phase-A ids (32 x 16)
    int h  = t >> 6;                       // phase-B head; o = t

    // hoist per-row constants for phase A into registers
    float myFs[8], myEi[8], myEib[8];
    #pragma unroll
    for (int hh = 0; hh < 8; hh++) {
        myFs[hh] = sFs[r][hh];
        myEi[hh] = sEi[r][hh];
        myEib[hh] = sEib[r][hh];
    }

    float zloc[8] = {};
    unsigned long long acc2[8] = {};      // 16 fp32 accumulators as 8 packed pairs

    for (int cbase = 0; cbase < N; cbase += CJ) {
        // ---- phase A: build P tile ----
        {
            int j = cbase + jj;
            unsigned bit = (sAdj[r][j >> 5] >> (j & 31)) & 1u;
            const float4* fd4 = (const float4*)&g_fd1[j * 8];
            const float4* ed4 = (const float4*)&g_ed1[j * 8];
            const float4* eb4 = (const float4*)&g_ed1b[j * 8];
            float fd[8], ed[8], eb[8];
            float4 v;
            v = fd4[0]; fd[0]=v.x; fd[1]=v.y; fd[2]=v.z; fd[3]=v.w;
            v = fd4[1]; fd[4]=v.x; fd[5]=v.y; fd[6]=v.z; fd[7]=v.w;
            v = ed4[0]; ed[0]=v.x; ed[1]=v.y; ed[2]=v.z; ed[3]=v.w;
            v = ed4[1]; ed[4]=v.x; ed[5]=v.y; ed[6]=v.z; ed[7]=v.w;
            v = eb4[0]; eb[0]=v.x; eb[1]=v.y; eb[2]=v.z; eb[3]=v.w;
            v = eb4[1]; eb[4]=v.x; eb[5]=v.y; eb[6]=v.z; eb[7]=v.w;
            #pragma unroll
            for (int hh = 0; hh < 8; hh++) {
                float s = myFs[hh] + fd[hh];
                float p = (s > 0.f) ? (myEi[hh] * ed[hh]) : (myEib[hh] * eb[hh]);
                p = bit ? p : 0.f;
                zloc[hh] += p;
                sP[jj][hh * 16 + r] = p;
            }
        }
        __syncthreads();
        // ---- phase B: acc[o][r] += P[jj][h][r] * Wh1[j][o], packed pairs ----
        {
            #pragma unroll 4
            for (int q = 0; q < CJ; q++) {
                float wh = g_Wh1[(size_t)(cbase + q) * HD + t];
                unsigned wu = __float_as_uint(wh);
                unsigned long long whd;
                asm("mov.b64 %0, {%1, %1};" : "=l"(whd) : "r"(wu));
                const double2* pd = (const double2*)&sP[q][h * 16];
                #pragma unroll
                for (int q4 = 0; q4 < 4; q4++) {
                    double2 d2 = pd[q4];
                    unsigned long long p0 = __double_as_longlong(d2.x);
                    unsigned long long p1 = __double_as_longlong(d2.y);
                    asm("fma.rn.f32x2 %0, %1, %2, %0;" : "+l"(acc2[q4*2+0]) : "l"(p0), "l"(whd));
                    asm("fma.rn.f32x2 %0, %1, %2, %0;" : "+l"(acc2[q4*2+1]) : "l"(p1), "l"(whd));
                }
            }
        }
        __syncthreads();
    }

    // ---- Z reduction ----
    #pragma unroll
    for (int hh = 0; hh < 8; hh++) atomicAdd(&sZ[r][hh], zloc[hh]);
    __syncthreads();

    // ---- epilogue: normalize + ELU ----
    #pragma unroll
    for (int q = 0; q < 8; q++) {
        unsigned long long a = acc2[q];
        float lo = __uint_as_float((unsigned)(a & 0xffffffffull));
        float hi = __uint_as_float((unsigned)(a >> 32));
        int r0 = q * 2, r1 = q * 2 + 1;
        float v0 = lo / sZ[r0][h];
        float v1 = hi / sZ[r1][h];
        v0 = (v0 > 0.f) ? v0 : (expf(v0) - 1.f);
        v1 = (v1 > 0.f) ? v1 : (expf(v1) - 1.f);
        g_hcat[(size_t)(i0 + r0) * HD + t] = v0;
        g_hcat[(size_t)(i0 + r1) * HD + t] = v1;
    }
}

// ---------------- K3: Wh2 = hcat @ W2, plus layer-2 logits ----------------
__global__ __launch_bounds__(256) void k_l2prep(const float* __restrict__ W2,
                                                const float* __restrict__ a2) {
    __shared__ float sH[16 * NFEAT];   // 32 KB
    __shared__ float sWh[16 * NCLASS];
    int i0 = blockIdx.x * 16;
    int t = threadIdx.x;
    for (int idx = t; idx < 16 * NFEAT; idx += 256)
        sH[idx] = g_hcat[(size_t)i0 * NFEAT + idx];
    __syncthreads();
    int r = t >> 4, c = t & 15;
    float acc = 0.f;
    #pragma unroll 4
    for (int f = 0; f < NFEAT; f++)
        acc += sH[r * NFEAT + f] * W2[f * NCLASS + c];
    g_Wh2[(i0 + r) * NCLASS + c] = acc;
    sWh[r * NCLASS + c] = acc;
    __syncthreads();
    if (t < 16) {
        float fs = 0.f, fd = 0.f;
        #pragma unroll
        for (int c2 = 0; c2 < NCLASS; c2++) {
            float v = sWh[t * NCLASS + c2];
            fs += v * a2[c2];
            fd += v * a2[NCLASS + c2];
        }
        int i = i0 + t;
        g_fs2[i] = fs; g_fd2[i] = fd;
        g_ed2[i] = expf(fd); g_ed2b[i] = expf(0.2f * fd);
    }
}

// ---------------- K4: fused attention layer 2 (no ELU) ----------------
__global__ __launch_bounds__(256) void k_att2(float* __restrict__ out) {
    __shared__ unsigned sAdj[16][128];
    __shared__ float sP2[256 * 17];     // [jj][r], padded
    __shared__ float sZ[16];
    __shared__ float sFs[16], sEi[16], sEib[16];
    int i0 = blockIdx.x * 16;
    int t = threadIdx.x;                // 256
    for (int idx = t; idx < 16 * 128; idx += 256)
        sAdj[idx >> 7][idx & 127] = g_adj[(size_t)(i0 + (idx >> 7)) * 128 + (idx & 127)];
    if (t < 16) {
        float fs = g_fs2[i0 + t];
        sFs[t] = fs; sEi[t] = expf(fs); sEib[t] = expf(0.2f * fs);
        sZ[t] = 0.f;
    }
    __syncthreads();
    int r = t >> 4, c = t & 15;
    float acc = 0.f;
    float zloc[16] = {};
    for (int cbase = 0; cbase < N; cbase += 256) {
        int j = cbase + t;
        float fd = g_fd2[j], ed = g_ed2[j], eb = g_ed2b[j];
        #pragma unroll
        for (int rr = 0; rr < 16; rr++) {
            unsigned bit = (sAdj[rr][j >> 5] >> (j & 31)) & 1u;
            float s = sFs[rr] + fd;
            float p = (s > 0.f) ? (sEi[rr] * ed) : (sEib[rr] * eb);
            p = bit ? p : 0.f;
            zloc[rr] += p;
            sP2[t * 17 + rr] = p;
        }
        __syncthreads();
        #pragma unroll 8
        for (int q = 0; q < 256; q++) {
            float wh = g_Wh2[(size_t)(cbase + q) * NCLASS + c];
            acc += sP2[q * 17 + r] * wh;
        }
        __syncthreads();
    }
    #pragma unroll
    for (int rr = 0; rr < 16; rr++) atomicAdd(&sZ[rr], zloc[rr]);
    __syncthreads();
    out[(size_t)(i0 + r) * NCLASS + c] = acc / sZ[r];
}

// ---------------- launcher ----------------
extern "C" void kernel_launch(void* const* d_in, const int* in_sizes, int n_in,
                              void* d_out, int out_size) {
    const float* x   = (const float*)d_in[0];
    const int*   adj = (const int*)  d_in[1];
    const float* W1  = (const float*)d_in[2];
    const float* a1  = (const float*)d_in[3];
    const float* W2  = (const float*)d_in[4];
    const float* a2  = (const float*)d_in[5];
    float* out = (float*)d_out;

    k_pack<<<N, 1024>>>(adj);
    k_w1r<<<(NHEADS * NFEAT * NHID) / 256, 256>>>(W1);
    k_gemm1<<<dim3(N / 64, HD / 64), 256>>>(x);
    k_logit1<<<N, 256>>>(a1);
    k_att1<<<N / RI, 512>>>();
    k_l2prep<<<N / 16, 256>>>(W2, a2);
    k_att2<<<N / 16, 256>>>(out);
}

// round 5
// speedup vs baseline: 1.1837x; 1.1837x over previous
#include <cuda_runtime.h>
#include <math.h>

#define N       4096
#define NFEAT   512
#define NHID    64
#define NHEADS  8
#define NCLASS  16
#define HD      512   /* NHEADS*NHID */

// ---------------- scratch (device globals; no allocations) ----------------
__device__ unsigned g_adj[N * 128];            // bit j of row i -> g_adj[i*128 + (j>>5)] >> (j&31)
__device__ float g_W1r[NFEAT * HD];            // [f][h*64+k]
__device__ float g_Wh1[N * HD];                // [i][h*64+k]
__device__ float g_fs1[N * NHEADS];            // raw src logit
__device__ float g_fd1[N * NHEADS];            // raw dst logit
__device__ float g_ed1[N * NHEADS];            // exp(fd)
__device__ float g_ed1b[N * NHEADS];           // exp(0.2*fd)
__device__ float g_hcat[N * HD];               // layer-1 output (post ELU)
__device__ float g_Wh2[N * NCLASS];
__device__ float g_fs2[N], g_fd2[N], g_ed2[N], g_ed2b[N];

// ---------------- K0: pack adjacency into bitmask ----------------
__global__ void k_pack(const int* __restrict__ adj) {
    int i = blockIdx.x;
    int t = threadIdx.x;                       // 1024 threads
    for (int base = 0; base < N; base += 1024) {
        int j = base + t;
        int v = adj[(size_t)i * N + j];
        unsigned m = __ballot_sync(0xffffffffu, v > 0);
        if ((t & 31) == 0) g_adj[i * 128 + (j >> 5)] = m;
    }
}

// ---------------- K0b: rearrange W1[h][f][k] -> W1r[f][h*64+k] ----------------
__global__ void k_w1r(const float* __restrict__ W1) {
    int idx = blockIdx.x * 256 + threadIdx.x;  // 262144 total
    int k = idx & 63;
    int f = (idx >> 6) & 511;
    int h = idx >> 15;
    g_W1r[f * HD + h * 64 + k] = W1[idx];
}

// ---------------- K1: Wh1 = x @ W1r   (4096x512 @ 512x512), f32x2 FMAs ----------------
__global__ __launch_bounds__(256) void k_gemm1(const float* __restrict__ x) {
    __shared__ __align__(16) float As[16 * 68];   // [k][row], padded (68*4 = 272B, 16B aligned per k)
    __shared__ __align__(16) float Bs[16 * 64];   // [k][col]
    int m0 = blockIdx.x * 64, n0 = blockIdx.y * 64;
    int t = threadIdx.x;
    int tr = t >> 4, tc = t & 15;
    unsigned long long acc2[4][2] = {};
    for (int kk = 0; kk < NFEAT; kk += 16) {
        {   // load A tile 64 rows x 16 k
            int c = t & 15, r0 = t >> 4;
            #pragma unroll
            for (int rr = 0; rr < 4; rr++) {
                int r = r0 + rr * 16;
                As[c * 68 + r] = x[(size_t)(m0 + r) * NFEAT + kk + c];
            }
        }
        {   // load B tile 16 k x 64 n
            int n = t & 63, k0 = t >> 6;
            #pragma unroll
            for (int q = 0; q < 4; q++) {
                int k = k0 + q * 4;
                Bs[k * 64 + n] = g_W1r[(size_t)(kk + k) * HD + n0 + n];
            }
        }
        __syncthreads();
        #pragma unroll
        for (int k = 0; k < 16; k++) {
            float4 a4 = *(const float4*)&As[k * 68 + tr * 4];
            ulonglong2 b2 = *(const ulonglong2*)&Bs[k * 64 + tc * 4];
            float av[4] = {a4.x, a4.y, a4.z, a4.w};
            #pragma unroll
            for (int i = 0; i < 4; i++) {
                unsigned au = __float_as_uint(av[i]);
                unsigned long long ad;
                asm("mov.b64 %0, {%1, %1};" : "=l"(ad) : "r"(au));
                asm("fma.rn.f32x2 %0, %1, %2, %0;" : "+l"(acc2[i][0]) : "l"(b2.x), "l"(ad));
                asm("fma.rn.f32x2 %0, %1, %2, %0;" : "+l"(acc2[i][1]) : "l"(b2.y), "l"(ad));
            }
        }
        __syncthreads();
    }
    #pragma unroll
    for (int i = 0; i < 4; i++) {
        int row = m0 + tr * 4 + i;
        float4 v;
        v.x = __uint_as_float((unsigned)(acc2[i][0] & 0xffffffffull));
        v.y = __uint_as_float((unsigned)(acc2[i][0] >> 32));
        v.z = __uint_as_float((unsigned)(acc2[i][1] & 0xffffffffull));
        v.w = __uint_as_float((unsigned)(acc2[i][1] >> 32));
        *(float4*)&g_Wh1[(size_t)row * HD + n0 + tc * 4] = v;
    }
}

// ---------------- K1b: layer-1 attention logits + exp tables ----------------
__global__ void k_logit1(const float* __restrict__ a1) {
    int i = blockIdx.x;
    int w = threadIdx.x >> 5, l = threadIdx.x & 31;   // warp w = head w
    const float* wh = &g_Wh1[(size_t)i * HD + w * 64];
    const float* a  = &a1[w * 128];
    float s = wh[l] * a[l]      + wh[l + 32] * a[l + 32];
    float d = wh[l] * a[64 + l] + wh[l + 32] * a[96 + l];
    #pragma unroll
    for (int o = 16; o; o >>= 1) {
        s += __shfl_xor_sync(0xffffffffu, s, o);
        d += __shfl_xor_sync(0xffffffffu, d, o);
    }
    if (l == 0) {
        g_fs1[i * 8 + w]  = s;
        g_fd1[i * 8 + w]  = d;
        g_ed1[i * 8 + w]  = expf(d);
        g_ed1b[i * 8 + w] = expf(0.2f * d);
    }
}

// ---------------- K2: fused masked-softmax attention, layer 1 ----------------
// 32 rows per block; 512 threads; CJ=16 j-columns per chunk.
// Per chunk: (1) batch-prefetch 16 Wh values into regs (MLP=16, latency hidden
// under phase A + BAR), (2) phase A builds P tile [16 j][8 h][32 r] in SMEM,
// (3) phase B: thread t owns output column o=t, accumulates 32 rows as 16
// packed fp32x2 pairs. Epilogue: /Z then ELU.
#define RI 32
#define CJ 16
__global__ __launch_bounds__(512, 1) void k_att1(void) {
    __shared__ unsigned sAdj[RI][128];                 // 16 KB
    __shared__ __align__(16) float sP[CJ][NHEADS * RI]; // 16 KB  [jj][h*32 + r]
    __shared__ float sZ[RI][8];
    __shared__ float sFs[RI][8], sEi[RI][8], sEib[RI][8];

    int i0 = blockIdx.x * RI;
    int t = threadIdx.x;

    for (int idx = t; idx < RI * 128; idx += 512)
        sAdj[idx >> 7][idx & 127] = g_adj[(size_t)(i0 + (idx >> 7)) * 128 + (idx & 127)];
    if (t < RI * 8) {
        int r = t >> 3, h = t & 7;
        float fs = g_fs1[(i0 + r) * 8 + h];
        sFs[r][h] = fs;
        sEi[r][h] = expf(fs);
        sEib[r][h] = expf(0.2f * fs);
        sZ[r][h] = 0.f;
    }
    __syncthreads();

    int jj = t >> 5, r = t & 31;          // phase-A ids (16 x 32)
    int h  = t >> 6;                       // phase-B head; o = t

    // per-row constants for phase A in registers
    float myFs[8], myEi[8], myEib[8];
    #pragma unroll
    for (int hh = 0; hh < 8; hh++) {
        myFs[hh] = sFs[r][hh];
        myEi[hh] = sEi[r][hh];
        myEib[hh] = sEib[r][hh];
    }

    float zloc[8] = {};
    unsigned long long acc2[16] = {};     // 32 fp32 accumulators as 16 packed pairs

    for (int cbase = 0; cbase < N; cbase += CJ) {
        // ---- prefetch Wh column t for the 16 j-rows of this chunk ----
        float wh[CJ];
        #pragma unroll
        for (int q = 0; q < CJ; q++)
            wh[q] = __ldg(&g_Wh1[(size_t)(cbase + q) * HD + t]);

        // ---- phase A: build P tile ----
        {
            int j = cbase + jj;
            unsigned bit = (sAdj[r][j >> 5] >> (j & 31)) & 1u;
            const float4* fd4 = (const float4*)&g_fd1[j * 8];
            const float4* ed4 = (const float4*)&g_ed1[j * 8];
            const float4* eb4 = (const float4*)&g_ed1b[j * 8];
            float fd[8], ed[8], eb[8];
            float4 v;
            v = fd4[0]; fd[0]=v.x; fd[1]=v.y; fd[2]=v.z; fd[3]=v.w;
            v = fd4[1]; fd[4]=v.x; fd[5]=v.y; fd[6]=v.z; fd[7]=v.w;
            v = ed4[0]; ed[0]=v.x; ed[1]=v.y; ed[2]=v.z; ed[3]=v.w;
            v = ed4[1]; ed[4]=v.x; ed[5]=v.y; ed[6]=v.z; ed[7]=v.w;
            v = eb4[0]; eb[0]=v.x; eb[1]=v.y; eb[2]=v.z; eb[3]=v.w;
            v = eb4[1]; eb[4]=v.x; eb[5]=v.y; eb[6]=v.z; eb[7]=v.w;
            #pragma unroll
            for (int hh = 0; hh < 8; hh++) {
                float s = myFs[hh] + fd[hh];
                float p = (s > 0.f) ? (myEi[hh] * ed[hh]) : (myEib[hh] * eb[hh]);
                p = bit ? p : 0.f;
                zloc[hh] += p;
                sP[jj][hh * RI + r] = p;
            }
        }
        __syncthreads();
        // ---- phase B: acc[o][r] += P[q][h][r] * Wh1[j][o], packed pairs ----
        #pragma unroll
        for (int q = 0; q < CJ; q++) {
            unsigned wu = __float_as_uint(wh[q]);
            unsigned long long whd;
            asm("mov.b64 %0, {%1, %1};" : "=l"(whd) : "r"(wu));
            const ulonglong2* pd = (const ulonglong2*)&sP[q][h * RI];
            #pragma unroll
            for (int p8 = 0; p8 < 8; p8++) {
                ulonglong2 d2 = pd[p8];
                asm("fma.rn.f32x2 %0, %1, %2, %0;" : "+l"(acc2[p8 * 2 + 0]) : "l"(d2.x), "l"(whd));
                asm("fma.rn.f32x2 %0, %1, %2, %0;" : "+l"(acc2[p8 * 2 + 1]) : "l"(d2.y), "l"(whd));
            }
        }
        __syncthreads();
    }

    // ---- Z reduction ----
    #pragma unroll
    for (int hh = 0; hh < 8; hh++) atomicAdd(&sZ[r][hh], zloc[hh]);
    __syncthreads();

    // ---- epilogue: normalize + ELU ----
    #pragma unroll
    for (int k = 0; k < 16; k++) {
        unsigned long long a = acc2[k];
        float lo = __uint_as_float((unsigned)(a & 0xffffffffull));
        float hi = __uint_as_float((unsigned)(a >> 32));
        int r0 = k * 2, r1 = k * 2 + 1;
        float v0 = lo / sZ[r0][h];
        float v1 = hi / sZ[r1][h];
        v0 = (v0 > 0.f) ? v0 : (expf(v0) - 1.f);
        v1 = (v1 > 0.f) ? v1 : (expf(v1) - 1.f);
        g_hcat[(size_t)(i0 + r0) * HD + t] = v0;
        g_hcat[(size_t)(i0 + r1) * HD + t] = v1;
    }
}

// ---------------- K3: Wh2 = hcat @ W2, plus layer-2 logits ----------------
__global__ __launch_bounds__(256) void k_l2prep(const float* __restrict__ W2,
                                                const float* __restrict__ a2) {
    __shared__ float sH[16 * NFEAT];   // 32 KB
    __shared__ float sWh[16 * NCLASS];
    int i0 = blockIdx.x * 16;
    int t = threadIdx.x;
    for (int idx = t; idx < 16 * NFEAT; idx += 256)
        sH[idx] = g_hcat[(size_t)i0 * NFEAT + idx];
    __syncthreads();
    int r = t >> 4, c = t & 15;
    float acc = 0.f;
    #pragma unroll 4
    for (int f = 0; f < NFEAT; f++)
        acc += sH[r * NFEAT + f] * W2[f * NCLASS + c];
    g_Wh2[(i0 + r) * NCLASS + c] = acc;
    sWh[r * NCLASS + c] = acc;
    __syncthreads();
    if (t < 16) {
        float fs = 0.f, fd = 0.f;
        #pragma unroll
        for (int c2 = 0; c2 < NCLASS; c2++) {
            float v = sWh[t * NCLASS + c2];
            fs += v * a2[c2];
            fd += v * a2[NCLASS + c2];
        }
        int i = i0 + t;
        g_fs2[i] = fs; g_fd2[i] = fd;
        g_ed2[i] = expf(fd); g_ed2b[i] = expf(0.2f * fd);
    }
}

// ---------------- K4: fused attention layer 2 (no ELU) ----------------
__global__ __launch_bounds__(256) void k_att2(float* __restrict__ out) {
    __shared__ unsigned sAdj[16][128];
    __shared__ float sP2[256 * 17];     // [jj][r], padded
    __shared__ float sZ[16];
    __shared__ float sFs[16], sEi[16], sEib[16];
    int i0 = blockIdx.x * 16;
    int t = threadIdx.x;                // 256
    for (int idx = t; idx < 16 * 128; idx += 256)
        sAdj[idx >> 7][idx & 127] = g_adj[(size_t)(i0 + (idx >> 7)) * 128 + (idx & 127)];
    if (t < 16) {
        float fs = g_fs2[i0 + t];
        sFs[t] = fs; sEi[t] = expf(fs); sEib[t] = expf(0.2f * fs);
        sZ[t] = 0.f;
    }
    __syncthreads();
    int r = t >> 4, c = t & 15;
    float acc = 0.f;
    float zloc[16] = {};
    for (int cbase = 0; cbase < N; cbase += 256) {
        int j = cbase + t;
        float fd = g_fd2[j], ed = g_ed2[j], eb = g_ed2b[j];
        #pragma unroll
        for (int rr = 0; rr < 16; rr++) {
            unsigned bit = (sAdj[rr][j >> 5] >> (j & 31)) & 1u;
            float s = sFs[rr] + fd;
            float p = (s > 0.f) ? (sEi[rr] * ed) : (sEib[rr] * eb);
            p = bit ? p : 0.f;
            zloc[rr] += p;
            sP2[t * 17 + rr] = p;
        }
        __syncthreads();
        #pragma unroll 8
        for (int q = 0; q < 256; q++) {
            float wh = g_Wh2[(size_t)(cbase + q) * NCLASS + c];
            acc += sP2[q * 17 + r] * wh;
        }
        __syncthreads();
    }
    #pragma unroll
    for (int rr = 0; rr < 16; rr++) atomicAdd(&sZ[rr], zloc[rr]);
    __syncthreads();
    out[(size_t)(i0 + r) * NCLASS + c] = acc / sZ[r];
}

// ---------------- launcher ----------------
extern "C" void kernel_launch(void* const* d_in, const int* in_sizes, int n_in,
                              void* d_out, int out_size) {
    const float* x   = (const float*)d_in[0];
    const int*   adj = (const int*)  d_in[1];
    const float* W1  = (const float*)d_in[2];
    const float* a1  = (const float*)d_in[3];
    const float* W2  = (const float*)d_in[4];
    const float* a2  = (const float*)d_in[5];
    float* out = (float*)d_out;

    k_pack<<<N, 1024>>>(adj);
    k_w1r<<<(NHEADS * NFEAT * NHID) / 256, 256>>>(W1);
    k_gemm1<<<dim3(N / 64, HD / 64), 256>>>(x);
    k_logit1<<<N, 256>>>(a1);
    k_att1<<<N / RI, 512>>>();
    k_l2prep<<<N / 16, 256>>>(W2, a2);
    k_att2<<<N / 16, 256>>>(out);
}